// round 1
// baseline (speedup 1.0000x reference)
#include <cuda_runtime.h>
#include <math.h>

// Problem constants
#define BB 4
#define TT 4096
#define DD 1024
#define DH 64
#define NROW (BB*TT)          // 16384
#define QT 32                 // T / 128 query tiles
#define CKT 4                 // key tiles per chunk
#define NCHUNK 8              // max chunks per q-tile (32/4)
#define SCALE 0.03125f        // D^-0.5 = 1/32

// ---------------- scratch (device globals; no allocation allowed) ----------------
__device__ float g_Q[NROW*DH];
__device__ float g_K[NROW*DH];
__device__ float g_V[NROW*DH];
__device__ float g_Op[(long)BB*QT*NCHUNK*128*DH];   // unnormalized partial O
__device__ float g_mp[BB*QT*NCHUNK*128];            // partial row max
__device__ float g_lp[BB*QT*NCHUNK*128];            // partial row sum

// =================================================================================
// Kernel 1: QKV projection.  Each block: 64 rows x 64 cols of Q,K,V.
// 256 threads: ty = tid/16 -> 4 rows each; tx = tid%16 -> 4 cols each.
// =================================================================================
#define PROJ_SMEM ((64*68 + 3*64*64)*4)

__global__ void proj_kernel(const float* __restrict__ x,
                            const float* __restrict__ Wq,
                            const float* __restrict__ Wk,
                            const float* __restrict__ Wv) {
    extern __shared__ float sm[];
    float* Xs = sm;               // [64][68]  (padded stride)
    float* Qw = sm + 64*68;       // [64][64]
    float* Kw = Qw + 64*64;
    float* Vw = Kw + 64*64;

    int tid = threadIdx.x;
    int tx = tid & 15, ty = tid >> 4;
    int r0 = ty*4, h0 = tx*4;
    long rowbase = (long)blockIdx.x * 64;

    float aq[4][4], ak[4][4], av[4][4];
    #pragma unroll
    for (int i=0;i<4;i++)
        #pragma unroll
        for (int j=0;j<4;j++) { aq[i][j]=0.f; ak[i][j]=0.f; av[i][j]=0.f; }

    for (int dc = 0; dc < DD; dc += 64) {
        __syncthreads();
        // X chunk: 64 rows x 64 d
        for (int i = tid; i < 1024; i += 256) {
            int r = i >> 4, d4 = (i & 15)*4;
            float4 v = *(const float4*)&x[(rowbase + r)*DD + dc + d4];
            float* p = &Xs[r*68 + d4];
            p[0]=v.x; p[1]=v.y; p[2]=v.z; p[3]=v.w;
        }
        // W chunks (already [d][h] row-major: direct copy)
        for (int i = tid; i < 1024; i += 256) {
            int d = i >> 4, h4 = (i & 15)*4;
            *(float4*)&Qw[d*64+h4] = *(const float4*)&Wq[(dc+d)*DH + h4];
            *(float4*)&Kw[d*64+h4] = *(const float4*)&Wk[(dc+d)*DH + h4];
            *(float4*)&Vw[d*64+h4] = *(const float4*)&Wv[(dc+d)*DH + h4];
        }
        __syncthreads();
        #pragma unroll 8
        for (int d = 0; d < 64; d++) {
            float xr[4];
            #pragma unroll
            for (int i=0;i<4;i++) xr[i] = Xs[(r0+i)*68 + d];
            float4 wq = *(float4*)&Qw[d*64+h0];
            float4 wk = *(float4*)&Kw[d*64+h0];
            float4 wv = *(float4*)&Vw[d*64+h0];
            #pragma unroll
            for (int i=0;i<4;i++) {
                aq[i][0] += xr[i]*wq.x; aq[i][1] += xr[i]*wq.y;
                aq[i][2] += xr[i]*wq.z; aq[i][3] += xr[i]*wq.w;
                ak[i][0] += xr[i]*wk.x; ak[i][1] += xr[i]*wk.y;
                ak[i][2] += xr[i]*wk.z; ak[i][3] += xr[i]*wk.w;
                av[i][0] += xr[i]*wv.x; av[i][1] += xr[i]*wv.y;
                av[i][2] += xr[i]*wv.z; av[i][3] += xr[i]*wv.w;
            }
        }
    }
    #pragma unroll
    for (int i=0;i<4;i++) {
        long row = rowbase + r0 + i;
        *(float4*)&g_Q[row*DH + h0] = make_float4(aq[i][0],aq[i][1],aq[i][2],aq[i][3]);
        *(float4*)&g_K[row*DH + h0] = make_float4(ak[i][0],ak[i][1],ak[i][2],ak[i][3]);
        *(float4*)&g_V[row*DH + h0] = make_float4(av[i][0],av[i][1],av[i][2],av[i][3]);
    }
}

// =================================================================================
// Kernel 2: flash-attention partials, split over key chunks for load balance.
// Block = (chunk c, q-tile qt, batch b). BM=128 queries, BN=128 keys/iter,
// up to CKT=4 key tiles per block. 256 threads, 8x8 S micro-tile, 8x4 O micro-tile.
// =================================================================================
#define QS_STRIDE 132
#define VS_STRIDE 68
#define FLASH_SMEM ((64*QS_STRIDE*2 + 128*VS_STRIDE + 128*128)*4)

__global__ void __launch_bounds__(256, 1) flash_kernel() {
    int c = blockIdx.x, qt = blockIdx.y, b = blockIdx.z;
    if (c * CKT > qt) return;   // chunk's first key tile must be <= qt (causal)

    extern __shared__ float sm[];
    float* Qs = sm;                       // [64][132]  transposed: Qs[d][m]
    float* Ks = Qs + 64*QS_STRIDE;        // [64][132]  transposed: Ks[d][n]
    float* Vs = Ks + 64*QS_STRIDE;        // [128][68]  Vs[n][d]
    float* Ps = Vs + 128*VS_STRIDE;       // [128 rows][32 float4-granules], XOR-swizzled

    int tid = threadIdx.x;
    int tx = tid & 15, ty = tid >> 4;
    int m0 = ty*8, n0 = tx*8, dh0 = tx*4;

    const float* Qg = g_Q + ((long)b*TT + (long)qt*128)*DH;

    // Load Q tile transposed, pre-scaled by D^-0.5
    for (int i = tid; i < 128*16; i += 256) {
        int m = i >> 4, d4 = (i & 15)*4;
        float4 v = *(const float4*)&Qg[m*DH + d4];
        Qs[(d4+0)*QS_STRIDE + m] = v.x*SCALE;
        Qs[(d4+1)*QS_STRIDE + m] = v.y*SCALE;
        Qs[(d4+2)*QS_STRIDE + m] = v.z*SCALE;
        Qs[(d4+3)*QS_STRIDE + m] = v.w*SCALE;
    }

    float acc[8][4];
    float mi[8], li[8];
    #pragma unroll
    for (int i=0;i<8;i++) {
        mi[i] = -1e30f; li[i] = 0.f;
        #pragma unroll
        for (int k=0;k<4;k++) acc[i][k] = 0.f;
    }

    int j1 = min(c*CKT + CKT, qt + 1);
    for (int j = c*CKT; j < j1; j++) {
        __syncthreads();   // prev-iter PV done (and Q load done on first iter)
        const float* Kg = g_K + ((long)b*TT + (long)j*128)*DH;
        const float* Vg = g_V + ((long)b*TT + (long)j*128)*DH;
        for (int i = tid; i < 128*16; i += 256) {
            int n = i >> 4, d4 = (i & 15)*4;
            float4 v = *(const float4*)&Kg[n*DH + d4];
            Ks[(d4+0)*QS_STRIDE + n] = v.x;
            Ks[(d4+1)*QS_STRIDE + n] = v.y;
            Ks[(d4+2)*QS_STRIDE + n] = v.z;
            Ks[(d4+3)*QS_STRIDE + n] = v.w;
            float4 w = *(const float4*)&Vg[n*DH + d4];
            *(float4*)&Vs[n*VS_STRIDE + d4] = w;
        }
        __syncthreads();

        // ---- S = (Q*scale) K^T : 8x8 per thread ----
        float s[8][8];
        #pragma unroll
        for (int i=0;i<8;i++)
            #pragma unroll
            for (int jj=0;jj<8;jj++) s[i][jj] = 0.f;

        #pragma unroll 2
        for (int d = 0; d < 64; d++) {
            float q[8], k[8];
            *(float4*)(q)   = *(const float4*)&Qs[d*QS_STRIDE + m0];
            *(float4*)(q+4) = *(const float4*)&Qs[d*QS_STRIDE + m0 + 4];
            *(float4*)(k)   = *(const float4*)&Ks[d*QS_STRIDE + n0];
            *(float4*)(k+4) = *(const float4*)&Ks[d*QS_STRIDE + n0 + 4];
            #pragma unroll
            for (int i=0;i<8;i++)
                #pragma unroll
                for (int jj=0;jj<8;jj++)
                    s[i][jj] += q[i]*k[jj];
        }

        // ---- causal mask (only diagonal tile) ----
        if (j == qt) {
            #pragma unroll
            for (int i=0;i<8;i++)
                #pragma unroll
                for (int jj=0;jj<8;jj++)
                    if (n0+jj > m0+i) s[i][jj] = -1e30f;
        }

        // ---- online softmax (row group = 16 lanes sharing ty) ----
        #pragma unroll
        for (int i=0;i<8;i++) {
            float rm = s[i][0];
            #pragma unroll
            for (int jj=1;jj<8;jj++) rm = fmaxf(rm, s[i][jj]);
            #pragma unroll
            for (int off=8; off>=1; off>>=1)
                rm = fmaxf(rm, __shfl_xor_sync(0xffffffffu, rm, off, 16));
            float mnew = fmaxf(mi[i], rm);
            float rs = 0.f;
            #pragma unroll
            for (int jj=0;jj<8;jj++) {
                s[i][jj] = __expf(s[i][jj] - mnew);
                rs += s[i][jj];
            }
            #pragma unroll
            for (int off=8; off>=1; off>>=1)
                rs += __shfl_xor_sync(0xffffffffu, rs, off, 16);
            float alpha = __expf(mi[i] - mnew);
            li[i] = li[i]*alpha + rs;
            mi[i] = mnew;
            #pragma unroll
            for (int k=0;k<4;k++) acc[i][k] *= alpha;
        }

        // ---- write P transposed+swizzled: Ps[n][granule (m/4) ^ ((n>>3)&7)] ----
        #pragma unroll
        for (int jj=0;jj<8;jj++) {
            int n = n0 + jj;
            int sw = (n >> 3) & 7;
            int g0 = (2*ty)     ^ sw;
            int g1 = (2*ty + 1) ^ sw;
            *(float4*)&Ps[n*128 + g0*4] = make_float4(s[0][jj],s[1][jj],s[2][jj],s[3][jj]);
            *(float4*)&Ps[n*128 + g1*4] = make_float4(s[4][jj],s[5][jj],s[6][jj],s[7][jj]);
        }
        __syncthreads();

        // ---- O += P V : 8 rows x 4 dh per thread ----
        #pragma unroll 2
        for (int n = 0; n < 128; n++) {
            int sw = (n >> 3) & 7;
            float p[8];
            *(float4*)(p)   = *(const float4*)&Ps[n*128 + (((2*ty)  ^sw))*4];
            *(float4*)(p+4) = *(const float4*)&Ps[n*128 + (((2*ty+1)^sw))*4];
            float4 v = *(const float4*)&Vs[n*VS_STRIDE + dh0];
            #pragma unroll
            for (int i=0;i<8;i++) {
                acc[i][0] += p[i]*v.x; acc[i][1] += p[i]*v.y;
                acc[i][2] += p[i]*v.z; acc[i][3] += p[i]*v.w;
            }
        }
    }

    // ---- write partials ----
    long pidx = (long)(b*QT + qt)*NCHUNK + c;
    #pragma unroll
    for (int i=0;i<8;i++) {
        long off = (pidx*128 + m0 + i)*DH + dh0;
        *(float4*)&g_Op[off] = make_float4(acc[i][0],acc[i][1],acc[i][2],acc[i][3]);
    }
    if (tx == 0) {
        #pragma unroll
        for (int i=0;i<8;i++) {
            g_mp[pidx*128 + m0 + i] = mi[i];
            g_lp[pidx*128 + m0 + i] = li[i];
        }
    }
}

// =================================================================================
// Kernel 3: merge partials across key chunks and normalize.
// =================================================================================
__global__ void merge_kernel(float* __restrict__ out) {
    int qt = blockIdx.x, b = blockIdx.y;
    int nc = qt/CKT + 1;           // ceil((qt+1)/CKT)
    __shared__ float ws[NCHUNK][128];
    __shared__ float invl[128];
    int tid = threadIdx.x;
    long pbase = (long)(b*QT + qt)*NCHUNK;

    if (tid < 128) {
        int m = tid;
        float mc[NCHUNK];
        float mx = -1e30f;
        for (int cc=0; cc<nc; cc++) {
            mc[cc] = g_mp[(pbase+cc)*128 + m];
            mx = fmaxf(mx, mc[cc]);
        }
        float lt = 0.f;
        for (int cc=0; cc<nc; cc++) {
            float w = __expf(mc[cc] - mx);
            ws[cc][m] = w;
            lt += w * g_lp[(pbase+cc)*128 + m];
        }
        invl[m] = 1.0f / lt;
    }
    __syncthreads();

    for (int i = tid; i < 128*64; i += 256) {
        int m = i >> 6, dh = i & 63;
        float o = 0.f;
        for (int cc=0; cc<nc; cc++)
            o += ws[cc][m] * g_Op[((pbase+cc)*128 + m)*DH + dh];
        out[((long)b*TT + (long)qt*128 + m)*DH + dh] = o * invl[m];
    }
}

// =================================================================================
extern "C" void kernel_launch(void* const* d_in, const int* in_sizes, int n_in,
                              void* d_out, int out_size) {
    const float* x  = (const float*)d_in[0];
    const float* Wq = (const float*)d_in[1];
    const float* Wk = (const float*)d_in[2];
    const float* Wv = (const float*)d_in[3];
    float* out = (float*)d_out;

    cudaFuncSetAttribute(proj_kernel,  cudaFuncAttributeMaxDynamicSharedMemorySize, PROJ_SMEM);
    cudaFuncSetAttribute(flash_kernel, cudaFuncAttributeMaxDynamicSharedMemorySize, FLASH_SMEM);

    proj_kernel<<<NROW/64, 256, PROJ_SMEM>>>(x, Wq, Wk, Wv);
    flash_kernel<<<dim3(NCHUNK, QT, BB), 256, FLASH_SMEM>>>();
    merge_kernel<<<dim3(QT, BB), 256>>>(out);
}

// round 2
// speedup vs baseline: 1.0206x; 1.0206x over previous
#include <cuda_runtime.h>
#include <math.h>

// Problem constants
#define BB 4
#define TT 4096
#define DD 1024
#define DH 64
#define NROW (BB*TT)          // 16384
#define QT 32                 // T / 128 query tiles
#define CKT 4                 // key tiles per chunk
#define NCHUNK 8              // max chunks per q-tile (32/4)
#define SCALE 0.03125f        // D^-0.5 = 1/32

typedef unsigned long long u64;

// ---------------- f32x2 packed-FMA helpers (FFMA2 in SASS) ----------------
__device__ __forceinline__ u64 pk2(float lo, float hi) {
    u64 r; asm("mov.b64 %0, {%1, %2};" : "=l"(r) : "f"(lo), "f"(hi)); return r;
}
__device__ __forceinline__ u64 bc2(float v) { return pk2(v, v); }
__device__ __forceinline__ void up2(u64 u, float& lo, float& hi) {
    asm("mov.b64 {%0, %1}, %2;" : "=f"(lo), "=f"(hi) : "l"(u));
}
__device__ __forceinline__ void fma2(u64& d, u64 a, u64 b) {
    asm("fma.rn.f32x2 %0, %1, %2, %3;" : "=l"(d) : "l"(a), "l"(b), "l"(d));
}
__device__ __forceinline__ void mul2(u64& d, u64 a) {
    asm("mul.rn.f32x2 %0, %1, %2;" : "=l"(d) : "l"(d), "l"(a));
}

// ---------------- scratch (device globals; no allocation allowed) ----------------
__device__ float g_Q[NROW*DH];
__device__ float g_K[NROW*DH];
__device__ float g_V[NROW*DH];
__device__ float g_Op[(long)BB*QT*NCHUNK*128*DH];   // unnormalized partial O
__device__ float g_mp[BB*QT*NCHUNK*128];            // partial row max
__device__ float g_lp[BB*QT*NCHUNK*128];            // partial row sum

// =================================================================================
// Kernel 1: QKV projection.  Each block: 64 rows x 64 cols of Q,K,V.
// 256 threads: ty = tid/16 -> 4 rows each; tx = tid%16 -> 4 cols (2 f32x2 pairs).
// =================================================================================
#define PROJ_SMEM ((64*68 + 3*64*64)*4)

__global__ void proj_kernel(const float* __restrict__ x,
                            const float* __restrict__ Wq,
                            const float* __restrict__ Wk,
                            const float* __restrict__ Wv) {
    extern __shared__ float sm[];
    float* Xs = sm;               // [64][68]  (padded stride)
    float* Qw = sm + 64*68;       // [64][64]
    float* Kw = Qw + 64*64;
    float* Vw = Kw + 64*64;

    int tid = threadIdx.x;
    int tx = tid & 15, ty = tid >> 4;
    int r0 = ty*4, h0 = tx*4;
    long rowbase = (long)blockIdx.x * 64;

    // packed accumulators: [row i][h-pair]
    u64 aq2[4][2], ak2[4][2], av2[4][2];
    #pragma unroll
    for (int i=0;i<4;i++)
        #pragma unroll
        for (int j=0;j<2;j++) { aq2[i][j]=0ull; ak2[i][j]=0ull; av2[i][j]=0ull; }

    for (int dc = 0; dc < DD; dc += 64) {
        __syncthreads();
        // X chunk: 64 rows x 64 d
        for (int i = tid; i < 1024; i += 256) {
            int r = i >> 4, d4 = (i & 15)*4;
            float4 v = *(const float4*)&x[(rowbase + r)*DD + dc + d4];
            float* p = &Xs[r*68 + d4];
            p[0]=v.x; p[1]=v.y; p[2]=v.z; p[3]=v.w;
        }
        // W chunks (already [d][h] row-major: direct copy)
        for (int i = tid; i < 1024; i += 256) {
            int d = i >> 4, h4 = (i & 15)*4;
            *(float4*)&Qw[d*64+h4] = *(const float4*)&Wq[(dc+d)*DH + h4];
            *(float4*)&Kw[d*64+h4] = *(const float4*)&Wk[(dc+d)*DH + h4];
            *(float4*)&Vw[d*64+h4] = *(const float4*)&Wv[(dc+d)*DH + h4];
        }
        __syncthreads();
        #pragma unroll 4
        for (int d = 0; d < 64; d++) {
            ulonglong2 wq = *(const ulonglong2*)&Qw[d*64+h0];
            ulonglong2 wk = *(const ulonglong2*)&Kw[d*64+h0];
            ulonglong2 wv = *(const ulonglong2*)&Vw[d*64+h0];
            #pragma unroll
            for (int i=0;i<4;i++) {
                u64 xb = bc2(Xs[(r0+i)*68 + d]);
                fma2(aq2[i][0], xb, wq.x); fma2(aq2[i][1], xb, wq.y);
                fma2(ak2[i][0], xb, wk.x); fma2(ak2[i][1], xb, wk.y);
                fma2(av2[i][0], xb, wv.x); fma2(av2[i][1], xb, wv.y);
            }
        }
    }
    #pragma unroll
    for (int i=0;i<4;i++) {
        long row = rowbase + r0 + i;
        float a0,a1,a2,a3;
        up2(aq2[i][0], a0, a1); up2(aq2[i][1], a2, a3);
        *(float4*)&g_Q[row*DH + h0] = make_float4(a0,a1,a2,a3);
        up2(ak2[i][0], a0, a1); up2(ak2[i][1], a2, a3);
        *(float4*)&g_K[row*DH + h0] = make_float4(a0,a1,a2,a3);
        up2(av2[i][0], a0, a1); up2(av2[i][1], a2, a3);
        *(float4*)&g_V[row*DH + h0] = make_float4(a0,a1,a2,a3);
    }
}

// =================================================================================
// Kernel 2: flash-attention partials, split over key chunks for load balance.
// Block = (chunk c, q-tile qt, batch b). BM=128 queries, BN=128 keys/iter.
// 256 threads; S micro-tile = 4 row-pairs x 8 cols (packed f32x2 over rows);
// O micro-tile = 4 row-pairs x 4 dh.
// =================================================================================
#define QS_STRIDE 132
#define VS_STRIDE 68
#define FLASH_SMEM ((64*QS_STRIDE*2 + 128*VS_STRIDE + 128*128)*4)

__global__ void __launch_bounds__(256, 1) flash_kernel() {
    int c = blockIdx.x, qt = blockIdx.y, b = blockIdx.z;
    if (c * CKT > qt) return;   // chunk's first key tile must be <= qt (causal)

    extern __shared__ float sm[];
    float* Qs = sm;                       // [64][132]  transposed: Qs[d][m]
    float* Ks = Qs + 64*QS_STRIDE;        // [64][132]  transposed: Ks[d][n]
    float* Vs = Ks + 64*QS_STRIDE;        // [128][68]  Vs[n][d]
    float* Ps = Vs + 128*VS_STRIDE;       // [128 rows][32 float4-granules], XOR-swizzled

    int tid = threadIdx.x;
    int tx = tid & 15, ty = tid >> 4;
    int m0 = ty*8, n0 = tx*8, dh0 = tx*4;

    const float* Qg = g_Q + ((long)b*TT + (long)qt*128)*DH;

    // Load Q tile transposed, pre-scaled by D^-0.5
    for (int i = tid; i < 128*16; i += 256) {
        int m = i >> 4, d4 = (i & 15)*4;
        float4 v = *(const float4*)&Qg[m*DH + d4];
        Qs[(d4+0)*QS_STRIDE + m] = v.x*SCALE;
        Qs[(d4+1)*QS_STRIDE + m] = v.y*SCALE;
        Qs[(d4+2)*QS_STRIDE + m] = v.z*SCALE;
        Qs[(d4+3)*QS_STRIDE + m] = v.w*SCALE;
    }

    u64 o2[4][4];                 // [row-pair][dh], packed over rows
    float mi[8], li[8];
    #pragma unroll
    for (int i=0;i<8;i++) { mi[i] = -1e30f; li[i] = 0.f; }
    #pragma unroll
    for (int ip=0;ip<4;ip++)
        #pragma unroll
        for (int k=0;k<4;k++) o2[ip][k] = 0ull;

    int j1 = min(c*CKT + CKT, qt + 1);
    for (int j = c*CKT; j < j1; j++) {
        __syncthreads();   // prev-iter PV done (and Q load done on first iter)
        const float* Kg = g_K + ((long)b*TT + (long)j*128)*DH;
        const float* Vg = g_V + ((long)b*TT + (long)j*128)*DH;
        for (int i = tid; i < 128*16; i += 256) {
            int n = i >> 4, d4 = (i & 15)*4;
            float4 v = *(const float4*)&Kg[n*DH + d4];
            Ks[(d4+0)*QS_STRIDE + n] = v.x;
            Ks[(d4+1)*QS_STRIDE + n] = v.y;
            Ks[(d4+2)*QS_STRIDE + n] = v.z;
            Ks[(d4+3)*QS_STRIDE + n] = v.w;
            float4 w = *(const float4*)&Vg[n*DH + d4];
            *(float4*)&Vs[n*VS_STRIDE + d4] = w;
        }
        __syncthreads();

        // ---- S = (Q*scale) K^T : packed over row-pairs ----
        u64 s2[4][8];
        #pragma unroll
        for (int ip=0;ip<4;ip++)
            #pragma unroll
            for (int jj=0;jj<8;jj++) s2[ip][jj] = 0ull;

        #pragma unroll 2
        for (int d = 0; d < 64; d++) {
            ulonglong2 qa = *(const ulonglong2*)&Qs[d*QS_STRIDE + m0];
            ulonglong2 qb = *(const ulonglong2*)&Qs[d*QS_STRIDE + m0 + 4];
            u64 q2[4] = {qa.x, qa.y, qb.x, qb.y};
            float4 ka = *(const float4*)&Ks[d*QS_STRIDE + n0];
            float4 kb = *(const float4*)&Ks[d*QS_STRIDE + n0 + 4];
            float kk[8] = {ka.x,ka.y,ka.z,ka.w,kb.x,kb.y,kb.z,kb.w};
            #pragma unroll
            for (int jj=0;jj<8;jj++) {
                u64 kbv = bc2(kk[jj]);
                #pragma unroll
                for (int ip=0;ip<4;ip++)
                    fma2(s2[ip][jj], q2[ip], kbv);
            }
        }

        // unpack packed scores to per-row floats
        float s[8][8];
        #pragma unroll
        for (int ip=0;ip<4;ip++)
            #pragma unroll
            for (int jj=0;jj<8;jj++)
                up2(s2[ip][jj], s[2*ip][jj], s[2*ip+1][jj]);

        // ---- causal mask (only diagonal tile) ----
        if (j == qt) {
            #pragma unroll
            for (int i=0;i<8;i++)
                #pragma unroll
                for (int jj=0;jj<8;jj++)
                    if (n0+jj > m0+i) s[i][jj] = -1e30f;
        }

        // ---- online softmax (row group = 16 lanes sharing ty) ----
        float alpha[8];
        #pragma unroll
        for (int i=0;i<8;i++) {
            float rm = s[i][0];
            #pragma unroll
            for (int jj=1;jj<8;jj++) rm = fmaxf(rm, s[i][jj]);
            #pragma unroll
            for (int off=8; off>=1; off>>=1)
                rm = fmaxf(rm, __shfl_xor_sync(0xffffffffu, rm, off, 16));
            float mnew = fmaxf(mi[i], rm);
            float rs = 0.f;
            #pragma unroll
            for (int jj=0;jj<8;jj++) {
                s[i][jj] = __expf(s[i][jj] - mnew);
                rs += s[i][jj];
            }
            #pragma unroll
            for (int off=8; off>=1; off>>=1)
                rs += __shfl_xor_sync(0xffffffffu, rs, off, 16);
            alpha[i] = __expf(mi[i] - mnew);
            li[i] = li[i]*alpha[i] + rs;
            mi[i] = mnew;
        }
        // rescale packed O accumulators
        #pragma unroll
        for (int ip=0;ip<4;ip++) {
            u64 a2 = pk2(alpha[2*ip], alpha[2*ip+1]);
            #pragma unroll
            for (int k=0;k<4;k++) mul2(o2[ip][k], a2);
        }

        // ---- write P transposed+swizzled: Ps[n][granule (m/4) ^ ((n>>3)&7)] ----
        #pragma unroll
        for (int jj=0;jj<8;jj++) {
            int n = n0 + jj;
            int sw = (n >> 3) & 7;
            int g0 = (2*ty)     ^ sw;
            int g1 = (2*ty + 1) ^ sw;
            *(float4*)&Ps[n*128 + g0*4] = make_float4(s[0][jj],s[1][jj],s[2][jj],s[3][jj]);
            *(float4*)&Ps[n*128 + g1*4] = make_float4(s[4][jj],s[5][jj],s[6][jj],s[7][jj]);
        }
        __syncthreads();

        // ---- O += P V : packed over row-pairs ----
        #pragma unroll 2
        for (int n = 0; n < 128; n++) {
            int sw = (n >> 3) & 7;
            ulonglong2 pa = *(const ulonglong2*)&Ps[n*128 + (((2*ty)  ^sw))*4];
            ulonglong2 pb = *(const ulonglong2*)&Ps[n*128 + (((2*ty+1)^sw))*4];
            u64 p2[4] = {pa.x, pa.y, pb.x, pb.y};
            float4 v = *(const float4*)&Vs[n*VS_STRIDE + dh0];
            u64 v2[4] = {bc2(v.x), bc2(v.y), bc2(v.z), bc2(v.w)};
            #pragma unroll
            for (int ip=0;ip<4;ip++)
                #pragma unroll
                for (int k=0;k<4;k++)
                    fma2(o2[ip][k], p2[ip], v2[k]);
        }
    }

    // ---- write partials ----
    long pidx = (long)(b*QT + qt)*NCHUNK + c;
    #pragma unroll
    for (int ip=0;ip<4;ip++) {
        float lo[4], hi[4];
        #pragma unroll
        for (int k=0;k<4;k++) up2(o2[ip][k], lo[k], hi[k]);
        long off0 = (pidx*128 + m0 + 2*ip)*DH + dh0;
        long off1 = (pidx*128 + m0 + 2*ip + 1)*DH + dh0;
        *(float4*)&g_Op[off0] = make_float4(lo[0],lo[1],lo[2],lo[3]);
        *(float4*)&g_Op[off1] = make_float4(hi[0],hi[1],hi[2],hi[3]);
    }
    if (tx == 0) {
        #pragma unroll
        for (int i=0;i<8;i++) {
            g_mp[pidx*128 + m0 + i] = mi[i];
            g_lp[pidx*128 + m0 + i] = li[i];
        }
    }
}

// =================================================================================
// Kernel 3: merge partials across key chunks and normalize.
// =================================================================================
__global__ void merge_kernel(float* __restrict__ out) {
    int qt = blockIdx.x, b = blockIdx.y;
    int nc = qt/CKT + 1;           // ceil((qt+1)/CKT)
    __shared__ float ws[NCHUNK][128];
    __shared__ float invl[128];
    int tid = threadIdx.x;
    long pbase = (long)(b*QT + qt)*NCHUNK;

    if (tid < 128) {
        int m = tid;
        float mc[NCHUNK];
        float mx = -1e30f;
        for (int cc=0; cc<nc; cc++) {
            mc[cc] = g_mp[(pbase+cc)*128 + m];
            mx = fmaxf(mx, mc[cc]);
        }
        float lt = 0.f;
        for (int cc=0; cc<nc; cc++) {
            float w = __expf(mc[cc] - mx);
            ws[cc][m] = w;
            lt += w * g_lp[(pbase+cc)*128 + m];
        }
        invl[m] = 1.0f / lt;
    }
    __syncthreads();

    for (int i = tid; i < 128*64; i += 256) {
        int m = i >> 6, dh = i & 63;
        float o = 0.f;
        for (int cc=0; cc<nc; cc++)
            o += ws[cc][m] * g_Op[((pbase+cc)*128 + m)*DH + dh];
        out[((long)b*TT + (long)qt*128 + m)*DH + dh] = o * invl[m];
    }
}

// =================================================================================
extern "C" void kernel_launch(void* const* d_in, const int* in_sizes, int n_in,
                              void* d_out, int out_size) {
    const float* x  = (const float*)d_in[0];
    const float* Wq = (const float*)d_in[1];
    const float* Wk = (const float*)d_in[2];
    const float* Wv = (const float*)d_in[3];
    float* out = (float*)d_out;

    cudaFuncSetAttribute(proj_kernel,  cudaFuncAttributeMaxDynamicSharedMemorySize, PROJ_SMEM);
    cudaFuncSetAttribute(flash_kernel, cudaFuncAttributeMaxDynamicSharedMemorySize, FLASH_SMEM);

    proj_kernel<<<NROW/64, 256, PROJ_SMEM>>>(x, Wq, Wk, Wv);
    flash_kernel<<<dim3(NCHUNK, QT, BB), 256, FLASH_SMEM>>>();
    merge_kernel<<<dim3(QT, BB), 256>>>(out);
}